// round 17
// baseline (speedup 1.0000x reference)
#include <cuda_runtime.h>
#include <cuda_bf16.h>
#include <math.h>
#include <stdint.h>

#define BATCH  512
#define TSTEPS 55
#define CDIM   512
#define DDIM   512
#define KDIM   64
#define NL     3
#define G4D    2048
#define HW     1536
#define NCTA   132
typedef __nv_bfloat16 bf16;

#define OFF_WX0 0u
#define OFF_WX1 1048576u
#define OFF_WX2 3145728u
#define OFF_WH0 6291456u
#define OFF_PROJ 9437184u
#define OFF_WR   10223616u
#define WTOT     10354688u

__device__ float g_pregate[(size_t)NL*TSTEPS*BATCH*G4D];
__device__ float g_whbuf[(size_t)NL*BATCH*G4D];
__device__ float g_prer[(size_t)TSTEPS*BATCH*256];
__device__ float g_hall[(size_t)(TSTEPS+1)*BATCH*HW];
__device__ bf16  g_hh[(size_t)(TSTEPS+1)*BATCH*HW];
__device__ bf16  g_hl[(size_t)(TSTEPS+1)*BATCH*HW];
__device__ float g_c[(size_t)NL*BATCH*DDIM];
__device__ float g_d[(size_t)NL*BATCH*KDIM];
__device__ bf16  g_xh[(size_t)BATCH*TSTEPS*CDIM];
__device__ bf16  g_xl[(size_t)BATCH*TSTEPS*CDIM];
__device__ bf16  g_pwh[WTOT];
__device__ bf16  g_pwl[WTOT];
__device__ int g_barcnt;
__device__ volatile unsigned g_bargen;

// ---- helpers ----
__device__ __forceinline__ uint32_t smem_u32(const void* p){
    uint32_t a; asm("{ .reg .u64 t; cvta.to.shared.u64 t, %1; cvt.u32.u64 %0, t; }":"=r"(a):"l"(p)); return a;
}
__device__ __forceinline__ uint32_t swz(uint32_t b){ return b ^ ((b>>3)&0x70u); }
__device__ __forceinline__ void cp16(uint32_t d, const void* s){
    asm volatile("cp.async.cg.shared.global [%0], [%1], 16;"::"r"(d),"l"(s));
}
__device__ __forceinline__ void cp_commit(){ asm volatile("cp.async.commit_group;":::"memory"); }
template<int N> __device__ __forceinline__ void cp_wait(){ asm volatile("cp.async.wait_group %0;"::"n"(N):"memory"); }
__device__ __forceinline__ void ldm4(uint32_t* r, uint32_t a){
    asm volatile("ldmatrix.sync.aligned.m8n8.x4.shared.b16 {%0,%1,%2,%3}, [%4];"
        :"=r"(r[0]),"=r"(r[1]),"=r"(r[2]),"=r"(r[3]):"r"(a));
}
__device__ __forceinline__ void mma16816(float* d, const uint32_t* a, uint32_t b0, uint32_t b1){
    asm volatile("mma.sync.aligned.m16n8k16.row.col.f32.bf16.bf16.f32 "
        "{%0,%1,%2,%3}, {%4,%5,%6,%7}, {%8,%9}, {%0,%1,%2,%3};"
        :"+f"(d[0]),"+f"(d[1]),"+f"(d[2]),"+f"(d[3])
        :"r"(a[0]),"r"(a[1]),"r"(a[2]),"r"(a[3]),"r"(b0),"r"(b1));
}
__device__ __forceinline__ void gbar(){
    __syncthreads();
    if (threadIdx.x == 0){
        unsigned g = g_bargen;
        __threadfence();
        if (atomicAdd(&g_barcnt, 1) == NCTA - 1){
            g_barcnt = 0;
            __threadfence();
            g_bargen = g + 1;
        } else {
            while (g_bargen == g){}
        }
        __threadfence();
    }
    __syncthreads();
}

// ---- init ----
__global__ void init_kernel(const float* __restrict__ ik){
    int i = blockIdx.x*blockDim.x + threadIdx.x;
    if (i < BATCH*HW){ g_hall[i]=0.f; g_hh[i]=__float2bfloat16(0.f); g_hl[i]=__float2bfloat16(0.f); }
    if (i < NL*BATCH*DDIM) g_c[i]=0.f;
    if (i < NL*BATCH*KDIM) g_d[i]=ik[i % (BATCH*KDIM)];
    if (i < 64*512){ g_pwh[OFF_WR+192*512+i]=__float2bfloat16(0.f); g_pwl[OFF_WR+192*512+i]=__float2bfloat16(0.f); }
    if (i == 0){ g_barcnt = 0; g_bargen = 0u; }
}

// ---- weight transpose+split ----
__global__ void wsplit_kernel(const float* __restrict__ W, bf16* __restrict__ hi, bf16* __restrict__ lo, int K, int N){
    __shared__ float t[32][33];
    int n0 = blockIdx.x*32, k0 = blockIdx.y*32;
    for (int i = threadIdx.y; i < 32; i += 8)
        t[i][threadIdx.x] = W[(size_t)(k0+i)*N + n0 + threadIdx.x];
    __syncthreads();
    for (int i = threadIdx.y; i < 32; i += 8){
        float v = t[threadIdx.x][i];
        bf16 h = __float2bfloat16(v);
        size_t o = (size_t)(n0+i)*K + k0 + threadIdx.x;
        hi[o] = h; lo[o] = __float2bfloat16(v - __bfloat162float(h));
    }
}
__global__ void xsplit_kernel(const float* __restrict__ x, bf16* __restrict__ hi, bf16* __restrict__ lo, int n){
    int i = blockIdx.x*blockDim.x + threadIdx.x;
    if (i < n){ float v = x[i]; bf16 h = __float2bfloat16(v); hi[i]=h; lo[i]=__float2bfloat16(v-__bfloat162float(h)); }
}

// ---- shared GEMM tile machinery ----
#define KC 64
#define TILE_B 16384
#define STAGE_B 65536
#define DSMEM (1024 + 2*STAGE_B)

__device__ __forceinline__ void ldchunk(uint32_t st, int tid,
    const bf16* Ah, const bf16* Al, const bf16* Bh, const bf16* Bl,
    int bm, int bn, int lda, int ldb, int kk)
{
#pragma unroll
    for (int i = 0; i < 2; i++){
        int idx = i*512 + tid;
        int row = idx>>3, g = idx&7;
        uint32_t so = swz((uint32_t)(row*128 + g*16));
        size_t ao = (size_t)(bm+row)*lda + kk + g*8;
        size_t bo = (size_t)(bn+row)*ldb + kk + g*8;
        cp16(st + so,            Ah + ao);
        cp16(st +   TILE_B + so, Al + ao);
        cp16(st + 2*TILE_B + so, Bh + bo);
        cp16(st + 3*TILE_B + so, Bl + bo);
    }
}

__device__ __forceinline__ void gemm_core(uint32_t sb, int tid,
    const bf16* Ah, const bf16* Al, const bf16* Bh, const bf16* Bl,
    int bm, int bn, int lda, int ldb, int nc, float acc[2][4][4])
{
    int lane = tid&31, wid = tid>>5;
    int mw = wid & 3, nw = wid >> 2;
#pragma unroll
    for (int i=0;i<2;i++)
#pragma unroll
        for (int j=0;j<4;j++)
#pragma unroll
            for (int q=0;q<4;q++) acc[i][j][q]=0.f;
    ldchunk(sb + 1024, tid, Ah, Al, Bh, Bl, bm, bn, lda, ldb, 0); cp_commit();
    if (nc > 1){ ldchunk(sb + 1024 + STAGE_B, tid, Ah, Al, Bh, Bl, bm, bn, lda, ldb, KC); cp_commit(); }
    int a_row = (lane & 15), a_cb = (lane >> 4) << 4;
    int b_row = (lane & 7) + ((lane >> 4) << 3), b_cb = ((lane >> 3) & 1) << 4;
    for (int c = 0; c < nc; c++){
        if (c+1 < nc) cp_wait<1>(); else cp_wait<0>();
        __syncthreads();
        uint32_t st = sb + 1024 + (c&1)*STAGE_B;
#pragma unroll
        for (int ks = 0; ks < 4; ks++){
            int kb = ks*32;
            uint32_t ah[2][4], al[2][4], bh[2][4], bl[2][4];
#pragma unroll
            for (int mf = 0; mf < 2; mf++){
                uint32_t off = swz((uint32_t)((mw*32 + mf*16 + a_row)*128 + kb + a_cb));
                ldm4(ah[mf], st + off);
                ldm4(al[mf], st + TILE_B + off);
            }
#pragma unroll
            for (int nf2 = 0; nf2 < 2; nf2++){
                uint32_t off = swz((uint32_t)((nw*32 + nf2*16 + b_row)*128 + kb + b_cb));
                ldm4(bh[nf2], st + 2*TILE_B + off);
                ldm4(bl[nf2], st + 3*TILE_B + off);
            }
#pragma unroll
            for (int mf = 0; mf < 2; mf++)
#pragma unroll
                for (int nf = 0; nf < 4; nf++){
                    uint32_t h0 = bh[nf>>1][(nf&1)*2], h1 = bh[nf>>1][(nf&1)*2+1];
                    uint32_t l0 = bl[nf>>1][(nf&1)*2], l1 = bl[nf>>1][(nf&1)*2+1];
                    mma16816(acc[mf][nf], ah[mf], h0, h1);
                    mma16816(acc[mf][nf], ah[mf], l0, l1);
                    mma16816(acc[mf][nf], al[mf], h0, h1);
                }
        }
        __syncthreads();
        if (c+2 < nc){ ldchunk(sb + 1024 + (c&1)*STAGE_B, tid, Ah, Al, Bh, Bl, bm, bn, lda, ldb, (c+2)*KC); cp_commit(); }
    }
}

// standalone GEMM kernel (precompute + projection): assign w/ permute + biases
__global__ __launch_bounds__(512, 1)
void tgemm_kernel(const bf16* Ah, const bf16* Al, const bf16* Bh, const bf16* Bl,
                  int segK, int lda, int ldb,
                  float* C, int ldc,
                  const float* __restrict__ bias1, const float* __restrict__ bias2,
                  int p1, int p2)
{
    extern __shared__ char smraw[];
    uint32_t sb = (smem_u32(smraw) + 1023u) & ~1023u;
    int tid = threadIdx.x, wid = tid>>5, lane = tid&31;
    int mw = wid & 3, nw = wid >> 2;
    int bm = blockIdx.y*128, bn = blockIdx.x*128;
    float acc[2][4][4];
    gemm_core(sb, tid, Ah, Al, Bh, Bl, bm, bn, lda, ldb, segK/KC, acc);
#pragma unroll
    for (int mf = 0; mf < 2; mf++){
        int r0 = bm + mw*32 + mf*16 + (lane>>2);
#pragma unroll
        for (int half = 0; half < 2; half++){
            int rm = r0 + half*8;
            float* Cr = C + ((size_t)(rm % p1)*p2 + (size_t)(rm / p1))*ldc;
#pragma unroll
            for (int nf = 0; nf < 4; nf++){
                int col = bn + nw*32 + nf*8 + (lane&3)*2;
                float v0 = acc[mf][nf][half*2], v1 = acc[mf][nf][half*2+1];
                if (bias1){ v0 += bias1[col]; v1 += bias1[col+1]; }
                if (bias2){ v0 += bias2[col]; v1 += bias2[col+1]; }
                Cr[col] = v0; Cr[col+1] = v1;
            }
        }
    }
}

// ---- persistent recurrence kernel ----
struct K12Smem { float hs[4][512]; float red[4][64]; float dsm[4][64]; };

__device__ void k12_phase(int l, int t, int cta,
    const float* wr, const float* wl0, const float* wl1, const float* wd, char* smraw)
{
    K12Smem* sm = (K12Smem*)smraw;
    int tid = threadIdx.x;
    int tx = tid & 63, ty = (tid>>6)&3, e = tid>>8;
    int b0 = cta*4;
    const float* hc = g_hall + (size_t)(t+1)*BATCH*HW;
    const float* hp = g_hall + (size_t)t*BATCH*HW;
    const float* pr = g_prer + (size_t)t*BATCH*256 + l*64;
    const float* gate = g_pregate + (size_t)l*TSTEPS*BATCH*G4D + (size_t)t*BATCH*G4D;
    const float* whg = (t > 0) ? (g_whbuf + (size_t)l*BATCH*G4D) : nullptr;
    float* cst = g_c + (size_t)l*BATCH*DDIM;
    float* dstate = g_d + (size_t)l*BATCH*KDIM;
    float* hout = g_hall + (size_t)(t+1)*BATCH*HW + l*DDIM;
    bf16* hh = g_hh + (size_t)(t+1)*BATCH*HW + l*DDIM;
    bf16* hl = g_hl + (size_t)(t+1)*BATCH*HW + l*DDIM;

    float acc = 0.f;
    if (e == 0) acc = __ldcg(&pr[(size_t)(b0+ty)*256 + tx]);
    for (int j = 0; j < l; j++)
        for (int s = 0; s < 2; s++){
            const float* src = s ? hp : hc;
            const float* W = s ? ((j==0)?wl0:wl1) : (wr + (size_t)(CDIM + j*DDIM)*KDIM);
            __syncthreads();
            for (int i = tid; i < 2048; i += 512)
                sm->hs[i>>9][i&511] = src[(size_t)(b0 + (i>>9))*HW + j*DDIM + (i&511)];
            __syncthreads();
            int cb = e*256;
            float p0=0.f,p1=0.f,p2=0.f,p3=0.f;
            for (int c = 0; c < 256; c += 4){
                p0 += sm->hs[ty][cb+c]  *W[(size_t)(cb+c)*KDIM+tx];
                p1 += sm->hs[ty][cb+c+1]*W[(size_t)(cb+c+1)*KDIM+tx];
                p2 += sm->hs[ty][cb+c+2]*W[(size_t)(cb+c+2)*KDIM+tx];
                p3 += sm->hs[ty][cb+c+3]*W[(size_t)(cb+c+3)*KDIM+tx];
            }
            float part = (p0+p1)+(p2+p3);
            if (e == 1) sm->red[ty][tx] = part;
            __syncthreads();
            if (e == 0) acc += (s ? (1.f/3.f) : 1.f) * (part + sm->red[ty][tx]);
        }
    __syncthreads();
    if (e == 0){
        float r = 1.f/(1.f+expf(-acc));
        size_t di = (size_t)(b0+ty)*KDIM + tx;
        float dn = __ldcg(&dstate[di])*r;
        __stcg(&dstate[di], dn);
        sm->dsm[ty][tx] = dn;
    }
    __syncthreads();
    int dd = tid;
    for (int r = 0; r < 4; r++){
        int b = b0 + r;
        float s0=0.f,s1=0.f,s2=0.f,s3=0.f;
#pragma unroll
        for (int k = 0; k < KDIM; k += 4){
            s0 += sm->dsm[r][k]  *wd[(size_t)k*DDIM+dd];
            s1 += sm->dsm[r][k+1]*wd[(size_t)(k+1)*DDIM+dd];
            s2 += sm->dsm[r][k+2]*wd[(size_t)(k+2)*DDIM+dd];
            s3 += sm->dsm[r][k+3]*wd[(size_t)(k+3)*DDIM+dd];
        }
        float dwd = tanhf((s0+s1)+(s2+s3));
        const float* g = gate + (size_t)b*G4D;
        float gf = __ldcg(&g[dd]), gi = __ldcg(&g[DDIM+dd]);
        float go = __ldcg(&g[2*DDIM+dd]), gc = __ldcg(&g[3*DDIM+dd]);
        if (whg){
            const float* w = whg + (size_t)b*G4D;
            gf += __ldcg(&w[dd]); gi += __ldcg(&w[DDIM+dd]);
            go += __ldcg(&w[2*DDIM+dd]); gc += __ldcg(&w[3*DDIM+dd]);
        }
        float f  = 1.f/(1.f+expf(-gf));
        float ii = 1.f/(1.f+expf(-gi));
        float o  = 1.f/(1.f+expf(-go));
        float cb = tanhf(gc);
        size_t ci = (size_t)b*DDIM + dd;
        float c = __ldcg(&cst[ci])*f + ii*cb + dwd;
        __stcg(&cst[ci], c);
        float h = o*tanhf(c);
        size_t ho = (size_t)b*HW + dd;
        hout[ho] = h;
        bf16 hb = __float2bfloat16(h);
        hh[ho] = hb; hl[ho] = __float2bfloat16(h - __bfloat162float(hb));
    }
}

__device__ void gemm_tile(char* smraw, const bf16* Ah, const bf16* Al,
    const bf16* Bh, const bf16* Bl, int bm, int bn, int ldb, float* C, int mode)
{
    uint32_t sb = (smem_u32(smraw) + 1023u) & ~1023u;
    int tid = threadIdx.x, wid = tid>>5, lane = tid&31;
    int mw = wid & 3, nw = wid >> 2;
    float acc[2][4][4];
    gemm_core(sb, tid, Ah, Al, Bh, Bl, bm, bn, HW, ldb, 512/KC, acc);
#pragma unroll
    for (int mf = 0; mf < 2; mf++){
        int r0 = bm + mw*32 + mf*16 + (lane>>2);
#pragma unroll
        for (int half = 0; half < 2; half++){
            float* Cr = C + (size_t)(r0 + half*8)*G4D;
#pragma unroll
            for (int nf = 0; nf < 4; nf++){
                int col = bn + nw*32 + nf*8 + (lane&3)*2;
                if (mode == 0){ Cr[col] += acc[mf][nf][half*2]; Cr[col+1] += acc[mf][nf][half*2+1]; }
                else { Cr[col] = acc[mf][nf][half*2]; Cr[col+1] = acc[mf][nf][half*2+1]; }
            }
        }
    }
}

__global__ __launch_bounds__(512, 1)
void persist_kernel(const float* wr0, const float* wr1, const float* wr2,
                    const float* wl0, const float* wl1, const float* wd)
{
    extern __shared__ char smraw[];
    int cta = blockIdx.x;
    const size_t SLAB = (size_t)TSTEPS*BATCH*G4D;
    for (int t = 0; t < TSTEPS; t++){
        const bf16* hh_c = g_hh + (size_t)(t+1)*BATCH*HW;
        const bf16* hl_c = g_hl + (size_t)(t+1)*BATCH*HW;
        const bf16* hh_p = g_hh + (size_t)t*BATCH*HW;
        const bf16* hl_p = g_hl + (size_t)t*BATCH*HW;
        float* slab1 = g_pregate + 1*SLAB + (size_t)t*BATCH*G4D;
        float* slab2 = g_pregate + 2*SLAB + (size_t)t*BATCH*G4D;

        if (cta < 128) k12_phase(0, t, cta, wr0, wl0, wl1, wd, smraw);
        gbar();
        for (int idx = cta; idx < 192; idx += NCTA){
            int grp = idx >> 6, r = idx & 63;
            int bm = (r>>4)*128, bn = (r&15)*128;
            if (grp == 0)      gemm_tile(smraw, hh_c, hl_c, g_pwh+OFF_WX1+CDIM, g_pwl+OFF_WX1+CDIM, bm, bn, 1024, slab1, 0);
            else if (grp == 1) gemm_tile(smraw, hh_c, hl_c, g_pwh+OFF_WX2+CDIM, g_pwl+OFF_WX2+CDIM, bm, bn, 1536, slab2, 0);
            else               gemm_tile(smraw, hh_c, hl_c, g_pwh+OFF_WH0, g_pwl+OFF_WH0, bm, bn, 512, g_whbuf, 1);
        }
        gbar();
        if (cta < 128) k12_phase(1, t, cta, wr1, wl0, wl1, wd, smraw);
        gbar();
        for (int idx = cta; idx < 192; idx += NCTA){
            int grp = idx >> 6, r = idx & 63;
            int bm = (r>>4)*128, bn = (r&15)*128;
            if (grp == 0)      gemm_tile(smraw, hh_c+512, hl_c+512, g_pwh+OFF_WX2+CDIM+512, g_pwl+OFF_WX2+CDIM+512, bm, bn, 1536, slab2, 0);
            else if (grp == 1) gemm_tile(smraw, hh_c+512, hl_c+512, g_pwh+OFF_WH0+1048576u, g_pwl+OFF_WH0+1048576u, bm, bn, 512, g_whbuf + (size_t)BATCH*G4D, 1);
            else               gemm_tile(smraw, hh_p+1024, hl_p+1024, g_pwh+OFF_WH0+2097152u, g_pwl+OFF_WH0+2097152u, bm, bn, 512, g_whbuf + 2*(size_t)BATCH*G4D, 1);
        }
        gbar();
        if (cta < 128) k12_phase(2, t, cta, wr2, wl0, wl1, wd, smraw);
        gbar();
    }
}

// ---- host ----
extern "C" void kernel_launch(void* const* d_in, const int* in_sizes, int n_in,
                              void* d_out, int out_size)
{
    (void)n_in; (void)out_size;
    const float* inputs    = (const float*)d_in[0];
    const float* init_keys = (const float*)d_in[1];
    const float *wx[NL], *wxb[NL], *whb[NL], *wr[NL], *wl[NL], *wh[NL];
    bool dict_order = (in_sizes[4] == 1048576);
    if (dict_order){
        for (int l = 0; l < NL; l++){
            int b0 = 2 + l*6;
            wx[l]=(const float*)d_in[b0];   wxb[l]=(const float*)d_in[b0+1];
            wh[l]=(const float*)d_in[b0+2]; whb[l]=(const float*)d_in[b0+3];
            wr[l]=(const float*)d_in[b0+4]; wl[l]=(const float*)d_in[b0+5];
        }
    } else {
        for (int l = 0; l < NL; l++){
            wx[l]=(const float*)d_in[2+2*l]; wxb[l]=(const float*)d_in[3+2*l];
            wh[l]=(const float*)d_in[8+2*l]; whb[l]=(const float*)d_in[9+2*l];
            wr[l]=(const float*)d_in[14+l];  wl[l]=(const float*)d_in[17+l];
        }
    }
    const float* wd    = (const float*)d_in[20];
    const float* projw = (const float*)d_in[21];
    const float* projb = (const float*)d_in[22];
    float* out = (float*)d_out;

    float *pregate,*prer;
    bf16 *hh,*hl,*xh,*xl,*pwh,*pwl;
    cudaGetSymbolAddress((void**)&pregate, g_pregate);
    cudaGetSymbolAddress((void**)&prer, g_prer);
    cudaGetSymbolAddress((void**)&hh, g_hh);
    cudaGetSymbolAddress((void**)&hl, g_hl);
    cudaGetSymbolAddress((void**)&xh, g_xh);
    cudaGetSymbolAddress((void**)&xl, g_xl);
    cudaGetSymbolAddress((void**)&pwh, g_pwh);
    cudaGetSymbolAddress((void**)&pwl, g_pwl);

    cudaFuncSetAttribute(tgemm_kernel, cudaFuncAttributeMaxDynamicSharedMemorySize, DSMEM);
    cudaFuncSetAttribute(persist_kernel, cudaFuncAttributeMaxDynamicSharedMemorySize, DSMEM);

    init_kernel<<<(BATCH*HW + 255)/256, 256>>>(init_keys);
    xsplit_kernel<<<(BATCH*TSTEPS*CDIM + 255)/256, 256>>>(inputs, xh, xl, BATCH*TSTEPS*CDIM);

    const uint32_t offwx[3] = {OFF_WX0, OFF_WX1, OFF_WX2};
    const int fin[3] = {512, 1024, 1536};
    dim3 wb(32, 8);
    for (int l = 0; l < NL; l++){
        wsplit_kernel<<<dim3(64, fin[l]/32), wb>>>(wx[l], pwh+offwx[l], pwl+offwx[l], fin[l], 2048);
        wsplit_kernel<<<dim3(64, 16), wb>>>(wh[l], pwh+OFF_WH0+l*1048576u, pwl+OFF_WH0+l*1048576u, 512, 2048);
        wsplit_kernel<<<dim3(2, 16), wb>>>(wr[l], pwh+OFF_WR+l*32768u, pwl+OFF_WR+l*32768u, 512, 64);
    }
    wsplit_kernel<<<dim3(16, 48), wb>>>(projw, pwh+OFF_PROJ, pwl+OFF_PROJ, 1536, 512);

    const int MBT = BATCH*TSTEPS;
    const size_t SLAB = (size_t)TSTEPS*BATCH*G4D;
    for (int l = 0; l < NL; l++)
        tgemm_kernel<<<dim3(16, MBT/128), 512, DSMEM>>>(
            xh, xl, pwh+offwx[l], pwl+offwx[l],
            512, 512, fin[l], pregate + (size_t)l*SLAB, G4D,
            wxb[l], whb[l], TSTEPS, BATCH);
    tgemm_kernel<<<dim3(2, MBT/128), 512, DSMEM>>>(
        xh, xl, pwh+OFF_WR, pwl+OFF_WR,
        512, 512, 512, prer, 256, nullptr, nullptr, TSTEPS, BATCH);

    persist_kernel<<<NCTA, 512, DSMEM>>>(wr[0], wr[1], wr[2], wl[0], wl[1], wd);

    tgemm_kernel<<<dim3(4, MBT/128), 512, DSMEM>>>(
        hh + (size_t)BATCH*HW, hl + (size_t)BATCH*HW, pwh+OFF_PROJ, pwl+OFF_PROJ,
        1536, HW, 1536, out, 512, projb, nullptr, BATCH, TSTEPS);
}